// round 1
// baseline (speedup 1.0000x reference)
#include <cuda_runtime.h>
#include <math.h>

// Problem constants (fixed by the reference)
#define Bn   4
#define Ln   6400
#define Cn   768
#define NHn  6
#define NPn  4
#define DHn  128
#define HSn  80
#define WSn  80
#define BLn  (Bn * Ln)          // 25600 rows
#define OAW  72                 // 48 offset cols + 24 attn-weight cols

// ---------------------------------------------------------------------------
// Scratch (static device globals; no runtime allocation)
// ---------------------------------------------------------------------------
__device__ float g_q[BLn * Cn];        // layernorm(x)
__device__ float g_f[BLn * Cn];        // layernorm(feat)
__device__ float g_value[BLn * Cn];    // value, laid out [B][NH][L][DH]
__device__ float g_attn[BLn * Cn];     // sampled attention pre-Wout, [B*L][C]
__device__ float g_offaw[BLn * OAW];   // q @ [Woff | Waw] + bias

// ---------------------------------------------------------------------------
// LayerNorm: one block per row of 768, 256 threads (3 elems/thread)
// ---------------------------------------------------------------------------
__global__ void __launch_bounds__(256) ln_kernel(
    const float* __restrict__ in, const float* __restrict__ w,
    const float* __restrict__ b, float* __restrict__ out)
{
    int row = blockIdx.x;
    int tid = threadIdx.x;
    const float* p = in + (size_t)row * Cn;
    float v0 = p[tid], v1 = p[tid + 256], v2 = p[tid + 512];
    float s1 = v0 + v1 + v2;
    float s2 = v0 * v0 + v1 * v1 + v2 * v2;
    #pragma unroll
    for (int o = 16; o > 0; o >>= 1) {
        s1 += __shfl_down_sync(0xffffffffu, s1, o);
        s2 += __shfl_down_sync(0xffffffffu, s2, o);
    }
    __shared__ float r1[8], r2[8];
    __shared__ float mu_s, rs_s;
    int wid = tid >> 5, lane = tid & 31;
    if (lane == 0) { r1[wid] = s1; r2[wid] = s2; }
    __syncthreads();
    if (tid == 0) {
        float t1 = 0.f, t2 = 0.f;
        #pragma unroll
        for (int i = 0; i < 8; i++) { t1 += r1[i]; t2 += r2[i]; }
        float mu  = t1 * (1.0f / Cn);
        float var = t2 * (1.0f / Cn) - mu * mu;
        mu_s = mu;
        rs_s = rsqrtf(var + 1e-6f);
    }
    __syncthreads();
    float mu = mu_s, rs = rs_s;
    float* o = out + (size_t)row * Cn;
    o[tid]       = (v0 - mu) * rs * w[tid]       + b[tid];
    o[tid + 256] = (v1 - mu) * rs * w[tid + 256] + b[tid + 256];
    o[tid + 512] = (v2 - mu) * rs * w[tid + 512] + b[tid + 512];
}

// ---------------------------------------------------------------------------
// SGEMM 128x128x8, 256 threads, 8x8 register tile. M=25600, N=768, K=768.
// EPI=0: C = A@B + bias, written transposed to value layout [B][NH][L][DH]
//        (block column cCol == head index, since BN == DH == 128).
// EPI=1: out = x + gamma * (A@B + bias), written to d_out [B*L][C].
// ---------------------------------------------------------------------------
template <int EPI>
__global__ void __launch_bounds__(256) sgemm_kernel(
    const float* __restrict__ A, const float* __restrict__ Bm,
    const float* __restrict__ bias, float* __restrict__ C,
    const float* __restrict__ xin, const float* __restrict__ gamma)
{
    const int K = Cn, N = Cn;
    __shared__ float As[8][128];
    __shared__ float Bs[8][128];
    int tid  = threadIdx.x;
    int cRow = blockIdx.y;              // M tile (0..199)
    int cCol = blockIdx.x;              // N tile (0..5)
    int threadCol = tid & 15;
    int threadRow = tid >> 4;
    int innerRowA = tid >> 1;
    int innerColA = (tid & 1) * 4;
    int innerRowB = tid >> 5;
    int innerColB = (tid & 31) * 4;

    const float* Ab = A  + (size_t)(cRow * 128) * K;
    const float* Bb = Bm + cCol * 128;

    float acc[8][8];
    #pragma unroll
    for (int i = 0; i < 8; i++)
        #pragma unroll
        for (int j = 0; j < 8; j++) acc[i][j] = 0.f;

    for (int k0 = 0; k0 < K; k0 += 8) {
        float4 a = *(const float4*)(Ab + (size_t)innerRowA * K + k0 + innerColA);
        As[innerColA + 0][innerRowA] = a.x;
        As[innerColA + 1][innerRowA] = a.y;
        As[innerColA + 2][innerRowA] = a.z;
        As[innerColA + 3][innerRowA] = a.w;
        *(float4*)&Bs[innerRowB][innerColB] =
            *(const float4*)(Bb + (size_t)(k0 + innerRowB) * N + innerColB);
        __syncthreads();
        #pragma unroll
        for (int k = 0; k < 8; k++) {
            float4 a0 = *(const float4*)&As[k][threadRow * 8];
            float4 a1 = *(const float4*)&As[k][threadRow * 8 + 4];
            float4 b0 = *(const float4*)&Bs[k][threadCol * 8];
            float4 b1 = *(const float4*)&Bs[k][threadCol * 8 + 4];
            float rm[8] = {a0.x, a0.y, a0.z, a0.w, a1.x, a1.y, a1.z, a1.w};
            float rn[8] = {b0.x, b0.y, b0.z, b0.w, b1.x, b1.y, b1.z, b1.w};
            #pragma unroll
            for (int i = 0; i < 8; i++)
                #pragma unroll
                for (int j = 0; j < 8; j++)
                    acc[i][j] += rm[i] * rn[j];
        }
        __syncthreads();
    }

    #pragma unroll
    for (int i = 0; i < 8; i++) {
        int m = cRow * 128 + threadRow * 8 + i;
        #pragma unroll
        for (int j0 = 0; j0 < 8; j0 += 4) {
            int nl = threadCol * 8 + j0;        // 0..127 within tile (== d for EPI 0)
            int n  = cCol * 128 + nl;           // global column
            float4 r;
            r.x = acc[i][j0 + 0] + bias[n + 0];
            r.y = acc[i][j0 + 1] + bias[n + 1];
            r.z = acc[i][j0 + 2] + bias[n + 2];
            r.w = acc[i][j0 + 3] + bias[n + 3];
            if (EPI == 0) {
                int b = m / Ln, l = m % Ln;
                size_t dst = ((size_t)(b * NHn + cCol) * Ln + l) * DHn + nl;
                *(float4*)&C[dst] = r;
            } else {
                size_t idx = (size_t)m * Cn + n;
                float4 xv = *(const float4*)&xin[idx];
                float4 gv = *(const float4*)&gamma[n];
                r.x = xv.x + gv.x * r.x;
                r.y = xv.y + gv.y * r.y;
                r.z = xv.z + gv.z * r.z;
                r.w = xv.w + gv.w * r.w;
                *(float4*)&C[idx] = r;
            }
        }
    }
}

// ---------------------------------------------------------------------------
// Offset/attn-weight projection: rows x 72, K=768. 16 rows per block,
// k-chunks of 64 staged in shared memory. Threads 0..71 each own one column.
// ---------------------------------------------------------------------------
__global__ void __launch_bounds__(128) offaw_kernel(
    const float* __restrict__ q, const float* __restrict__ Woff,
    const float* __restrict__ boff, const float* __restrict__ Waw,
    const float* __restrict__ baw, float* __restrict__ offaw)
{
    __shared__ float qs[16][64];
    __shared__ float ws[64][OAW];
    int tid  = threadIdx.x;
    int row0 = blockIdx.x * 16;
    int j    = tid;
    float acc[16];
    if (j < OAW) {
        float bb = (j < 48) ? boff[j] : baw[j - 48];
        #pragma unroll
        for (int r = 0; r < 16; r++) acc[r] = bb;
    }
    for (int kc = 0; kc < Cn; kc += 64) {
        __syncthreads();
        #pragma unroll
        for (int idx = tid; idx < 16 * 64; idx += 128) {
            int r = idx >> 6, kk = idx & 63;
            qs[r][kk] = q[(size_t)(row0 + r) * Cn + kc + kk];
        }
        for (int idx = tid; idx < 64 * OAW; idx += 128) {
            int k = idx / OAW, jj = idx % OAW;
            ws[k][jj] = (jj < 48) ? Woff[(kc + k) * 48 + jj]
                                  : Waw[(kc + k) * 24 + (jj - 48)];
        }
        __syncthreads();
        if (j < OAW) {
            #pragma unroll 8
            for (int kk = 0; kk < 64; kk++) {
                float w = ws[kk][j];
                #pragma unroll
                for (int r = 0; r < 16; r++) acc[r] += qs[r][kk] * w;
            }
        }
    }
    if (j < OAW) {
        #pragma unroll
        for (int r = 0; r < 16; r++)
            offaw[(size_t)(row0 + r) * OAW + j] = acc[r];
    }
}

// ---------------------------------------------------------------------------
// Bilinear sampling + softmax + weighted accumulation.
// One warp per (b, l, h); each lane owns 4 of the 128 DH channels (float4).
// ---------------------------------------------------------------------------
__global__ void __launch_bounds__(256) sample_kernel(
    const float* __restrict__ refp, const float* __restrict__ offaw,
    const float* __restrict__ value, float* __restrict__ attn)
{
    int gw   = (blockIdx.x * 256 + threadIdx.x) >> 5;
    int lane = threadIdx.x & 31;
    if (gw >= BLn * NHn) return;
    int h  = gw % NHn;
    int bl = gw / NHn;
    int b  = bl / Ln;

    const float* oa = offaw + (size_t)bl * OAW;
    // softmax over this head's 4 attention logits
    float lg0 = oa[48 + h * 4 + 0];
    float lg1 = oa[48 + h * 4 + 1];
    float lg2 = oa[48 + h * 4 + 2];
    float lg3 = oa[48 + h * 4 + 3];
    float mx = fmaxf(fmaxf(lg0, lg1), fmaxf(lg2, lg3));
    float e0 = expf(lg0 - mx), e1 = expf(lg1 - mx);
    float e2 = expf(lg2 - mx), e3 = expf(lg3 - mx);
    float inv = 1.0f / (e0 + e1 + e2 + e3);
    float aws[4] = {e0 * inv, e1 * inv, e2 * inv, e3 * inv};

    float rx = refp[bl * 2 + 0];
    float ry = refp[bl * 2 + 1];
    const float* vb = value + ((size_t)(b * NHn + h)) * Ln * DHn;

    float4 acc = make_float4(0.f, 0.f, 0.f, 0.f);
    #pragma unroll
    for (int p = 0; p < NPn; p++) {
        float ox = oa[h * 8 + p * 2 + 0];
        float oy = oa[h * 8 + p * 2 + 1];
        float lx = (rx + ox / (float)WSn) * (float)WSn - 0.5f;
        float ly = (ry + oy / (float)HSn) * (float)HSn - 0.5f;
        float x0f = floorf(lx), y0f = floorf(ly);
        float tx = lx - x0f, ty = ly - y0f;
        int x0 = (int)x0f, y0 = (int)y0f;
        float wp = aws[p];
        float cw[4] = {(1.f - tx) * (1.f - ty) * wp,
                       tx * (1.f - ty) * wp,
                       (1.f - tx) * ty * wp,
                       tx * ty * wp};
        int cx[4] = {x0, x0 + 1, x0,     x0 + 1};
        int cy[4] = {y0, y0,     y0 + 1, y0 + 1};
        #pragma unroll
        for (int c = 0; c < 4; c++) {
            int xi = cx[c], yi = cy[c];
            if (xi >= 0 && xi < WSn && yi >= 0 && yi < HSn) {
                const float4 v = *(const float4*)(vb + (size_t)(yi * WSn + xi) * DHn + lane * 4);
                float w = cw[c];
                acc.x += w * v.x; acc.y += w * v.y;
                acc.z += w * v.z; acc.w += w * v.w;
            }
        }
    }
    *(float4*)(attn + (size_t)bl * Cn + h * DHn + lane * 4) = acc;
}

// ---------------------------------------------------------------------------
// Launch
// ---------------------------------------------------------------------------
extern "C" void kernel_launch(void* const* d_in, const int* in_sizes, int n_in,
                              void* d_out, int out_size)
{
    const float* x     = (const float*)d_in[0];
    const float* refp  = (const float*)d_in[1];
    const float* feat  = (const float*)d_in[2];
    // d_in[3] spatial_shapes, d_in[4] level_start_index: static, baked in
    const float* qn_w  = (const float*)d_in[5];
    const float* qn_b  = (const float*)d_in[6];
    const float* fn_w  = (const float*)d_in[7];
    const float* fn_b  = (const float*)d_in[8];
    const float* gamma = (const float*)d_in[9];
    const float* Wv    = (const float*)d_in[10];
    const float* bv    = (const float*)d_in[11];
    const float* Woff  = (const float*)d_in[12];
    const float* boff  = (const float*)d_in[13];
    const float* Waw   = (const float*)d_in[14];
    const float* baw   = (const float*)d_in[15];
    const float* Wout  = (const float*)d_in[16];
    const float* bout  = (const float*)d_in[17];
    float* out = (float*)d_out;

    float *q, *f, *val, *attn, *oaw;
    cudaGetSymbolAddress((void**)&q,    g_q);
    cudaGetSymbolAddress((void**)&f,    g_f);
    cudaGetSymbolAddress((void**)&val,  g_value);
    cudaGetSymbolAddress((void**)&attn, g_attn);
    cudaGetSymbolAddress((void**)&oaw,  g_offaw);

    // 1) LayerNorms
    ln_kernel<<<BLn, 256>>>(x,    qn_w, qn_b, q);
    ln_kernel<<<BLn, 256>>>(feat, fn_w, fn_b, f);

    // 2) value = f @ Wv + bv  (written transposed per head)
    dim3 gg(Cn / 128, BLn / 128);
    sgemm_kernel<0><<<gg, 256>>>(f, Wv, bv, val, nullptr, nullptr);

    // 3) offsets + attn-weight logits
    offaw_kernel<<<BLn / 16, 128>>>(q, Woff, boff, Waw, baw, oaw);

    // 4) softmax + bilinear sampling
    sample_kernel<<<(BLn * NHn) / 8, 256>>>(refp, oaw, val, attn);

    // 5) out = x + gamma * (attn @ Wout + bout)
    sgemm_kernel<1><<<gg, 256>>>(attn, Wout, bout, out, x, gamma);
}

// round 4
// speedup vs baseline: 3.9450x; 3.9450x over previous
#include <cuda_runtime.h>
#include <cuda_bf16.h>
#include <math.h>
#include <stdint.h>

// Problem constants
#define Bn   4
#define Ln   6400
#define Cn   768
#define NHn  6
#define NPn  4
#define DHn  128
#define HSn  80
#define WSn  80
#define BLn  (Bn * Ln)          // 25600 rows
#define OAW  72                 // 48 offset cols + 24 attn-weight cols

// ---------------------------------------------------------------------------
// Scratch (static device globals)
// ---------------------------------------------------------------------------
__device__ __nv_bfloat16 g_qb[BLn * Cn];      // layernorm(x), bf16
__device__ __nv_bfloat16 g_fb[BLn * Cn];      // layernorm(feat), bf16
__device__ __nv_bfloat16 g_val[BLn * Cn];     // value [B][NH][L][DH], bf16
__device__ __nv_bfloat16 g_attn[BLn * Cn];    // sampled attn [B*L][C], bf16
__device__ float         g_offaw[BLn * OAW];  // offsets+logits, fp32
__device__ __nv_bfloat16 g_wvt[Cn * Cn];      // Wv^T  [N][K] bf16
__device__ __nv_bfloat16 g_woutt[Cn * Cn];    // Wout^T [N][K] bf16
__device__ __nv_bfloat16 g_wct[128 * Cn];     // [Woff|Waw|0]^T [128][K] bf16
__device__ float         g_bc[OAW];           // combined bias

// ---------------------------------------------------------------------------
// PTX helpers (portable: mma.sync + ldmatrix + cp.async, all sm_80+)
// ---------------------------------------------------------------------------
__device__ __forceinline__ uint32_t s2u(const void* p) {
    uint32_t a;
    asm("{ .reg .u64 t; cvta.to.shared.u64 t, %1; cvt.u32.u64 %0, t; }"
        : "=r"(a) : "l"(p));
    return a;
}

__device__ __forceinline__ void ldsm_x4(uint32_t* r, uint32_t addr) {
    asm volatile("ldmatrix.sync.aligned.m8n8.x4.shared.b16 {%0,%1,%2,%3}, [%4];"
        : "=r"(r[0]), "=r"(r[1]), "=r"(r[2]), "=r"(r[3]) : "r"(addr));
}
__device__ __forceinline__ void mma_bf16(float* c, const uint32_t* a, const uint32_t* b) {
    asm volatile(
        "mma.sync.aligned.m16n8k16.row.col.f32.bf16.bf16.f32 "
        "{%0,%1,%2,%3}, {%4,%5,%6,%7}, {%8,%9}, {%0,%1,%2,%3};"
        : "+f"(c[0]), "+f"(c[1]), "+f"(c[2]), "+f"(c[3])
        : "r"(a[0]), "r"(a[1]), "r"(a[2]), "r"(a[3]), "r"(b[0]), "r"(b[1]));
}
__device__ __forceinline__ void cp16(uint32_t smem, const void* g) {
    asm volatile("cp.async.cg.shared.global [%0], [%1], 16;" :: "r"(smem), "l"(g));
}
#define CP_COMMIT()  asm volatile("cp.async.commit_group;" ::: "memory")
#define CP_WAIT1()   asm volatile("cp.async.wait_group 1;" ::: "memory")
#define CP_WAIT0()   asm volatile("cp.async.wait_group 0;" ::: "memory")

// ---------------------------------------------------------------------------
// LayerNorm: one block per row of 768, 256 threads, bf16 output
// ---------------------------------------------------------------------------
__global__ void __launch_bounds__(256) ln_kernel(
    const float* __restrict__ in, const float* __restrict__ w,
    const float* __restrict__ b, __nv_bfloat16* __restrict__ out)
{
    int row = blockIdx.x;
    int tid = threadIdx.x;
    const float* p = in + (size_t)row * Cn;
    float v0 = p[tid], v1 = p[tid + 256], v2 = p[tid + 512];
    float s1 = v0 + v1 + v2;
    float s2 = v0 * v0 + v1 * v1 + v2 * v2;
    #pragma unroll
    for (int o = 16; o > 0; o >>= 1) {
        s1 += __shfl_down_sync(0xffffffffu, s1, o);
        s2 += __shfl_down_sync(0xffffffffu, s2, o);
    }
    __shared__ float r1[8], r2[8];
    __shared__ float mu_s, rs_s;
    int wid = tid >> 5, lane = tid & 31;
    if (lane == 0) { r1[wid] = s1; r2[wid] = s2; }
    __syncthreads();
    if (tid == 0) {
        float t1 = 0.f, t2 = 0.f;
        #pragma unroll
        for (int i = 0; i < 8; i++) { t1 += r1[i]; t2 += r2[i]; }
        float mu  = t1 * (1.0f / Cn);
        float var = t2 * (1.0f / Cn) - mu * mu;
        mu_s = mu;
        rs_s = rsqrtf(var + 1e-6f);
    }
    __syncthreads();
    float mu = mu_s, rs = rs_s;
    __nv_bfloat16* o = out + (size_t)row * Cn;
    o[tid]       = __float2bfloat16((v0 - mu) * rs * w[tid]       + b[tid]);
    o[tid + 256] = __float2bfloat16((v1 - mu) * rs * w[tid + 256] + b[tid + 256]);
    o[tid + 512] = __float2bfloat16((v2 - mu) * rs * w[tid + 512] + b[tid + 512]);
}

// ---------------------------------------------------------------------------
// Weight prep: transpose 768x768 fp32 -> [N][K] bf16
// ---------------------------------------------------------------------------
__global__ void __launch_bounds__(1024) wt_kernel(
    const float* __restrict__ W, __nv_bfloat16* __restrict__ Wt)
{
    __shared__ float t[32][33];
    int tx = threadIdx.x, ty = threadIdx.y;
    int bx = blockIdx.x, by = blockIdx.y;
    t[ty][tx] = W[(size_t)(by * 32 + ty) * Cn + bx * 32 + tx];
    __syncthreads();
    Wt[(size_t)(bx * 32 + ty) * Cn + by * 32 + tx] = __float2bfloat16(t[tx][ty]);
}

// Combine Woff (768x48) and Waw (768x24) into [128][768] bf16 (zero-padded)
__global__ void __launch_bounds__(256) comb_kernel(
    const float* __restrict__ Woff, const float* __restrict__ boff,
    const float* __restrict__ Waw,  const float* __restrict__ baw,
    __nv_bfloat16* __restrict__ Wct, float* __restrict__ bc)
{
    int idx = blockIdx.x * 256 + threadIdx.x;   // 0 .. 128*768-1
    int j = idx / Cn, k = idx % Cn;
    float v = 0.f;
    if (j < 48)       v = Woff[(size_t)k * 48 + j];
    else if (j < OAW) v = Waw[(size_t)k * 24 + (j - 48)];
    Wct[idx] = __float2bfloat16(v);
    if (idx < OAW) bc[idx] = (idx < 48) ? boff[idx] : baw[idx - 48];
}

// ---------------------------------------------------------------------------
// HMMA bf16 GEMM: C[M,128*gx] = A[M,768] @ Bt^T. CTA tile 128x128, BK=32,
// 8 warps (4 along M x 2 along N), warp tile 32x64, cp.async double buffer.
// SMEM row pitch = 40 halves (80 B) -> conflict-free ldmatrix.
// B stored [N][K] -> NON-trans ldmatrix gives the canonical col-major B frag.
// EPI 0: value = acc + bias  -> bf16, layout [B][NH=cCol][L][DH]
// EPI 1: out   = x + gamma * (acc + bias) -> fp32 [M][768]
// EPI 2: offaw = acc + bias (cols < 72)   -> fp32 [M][72]
// ---------------------------------------------------------------------------
#define PITCH 40          // halves per SMEM row (80 B)
#define BUFH  (128 * PITCH)

template <int EPI>
__global__ void __launch_bounds__(256) gemm_hmma(
    const __nv_bfloat16* __restrict__ A,
    const __nv_bfloat16* __restrict__ Bt,
    const float* __restrict__ bias,
    void* __restrict__ Cout,
    const float* __restrict__ xin,
    const float* __restrict__ gamma)
{
    __shared__ __align__(16) __nv_bfloat16 As[2][BUFH];
    __shared__ __align__(16) __nv_bfloat16 Bs[2][BUFH];

    const int tid  = threadIdx.x;
    const int wid  = tid >> 5, lane = tid & 31;
    const int wm   = wid & 3;          // 0..3  (32 rows each)
    const int wn   = wid >> 2;         // 0..1  (64 cols each)
    const int cCol = blockIdx.x, cRow = blockIdx.y;

    const __nv_bfloat16* Ab = A  + (size_t)cRow * 128 * Cn;
    const __nv_bfloat16* Bb = Bt + (size_t)cCol * 128 * Cn;
    const uint32_t aS = s2u(As), bS = s2u(Bs);

    // per-thread gmem/smem chunk coords (2 chunks of 16B per matrix per stage)
    const int row_c[2] = { tid >> 2, (tid + 256) >> 2 };
    const int q_c[2]   = { tid & 3,  tid & 3 };

    auto issue = [&](int i) {
        int buf = i & 1, k0 = i * 32;
        uint32_t ab = aS + buf * (BUFH * 2);
        uint32_t bb = bS + buf * (BUFH * 2);
        #pragma unroll
        for (int it = 0; it < 2; it++) {
            int row = row_c[it], q = q_c[it];
            uint32_t so = (uint32_t)(row * PITCH + q * 8) * 2;
            cp16(ab + so, Ab + (size_t)row * Cn + k0 + q * 8);
            cp16(bb + so, Bb + (size_t)row * Cn + k0 + q * 8);
        }
    };

    float acc[2][8][4];
    #pragma unroll
    for (int mi = 0; mi < 2; mi++)
        #pragma unroll
        for (int n8 = 0; n8 < 8; n8++)
            #pragma unroll
            for (int j = 0; j < 4; j++) acc[mi][n8][j] = 0.f;

    // ldmatrix lane address components
    const int lrow = lane & 7, grp = lane >> 3;
    const int rA = wm * 32 + (grp & 1) * 8 + lrow;         // + mi*16
    const int cA = (grp >> 1) * 8;                         // + kk
    const int rB = wn * 64 + ((lane >> 4) & 1) * 8 + lrow; // + nj*16
    const int cB = (grp & 1) * 8;                          // + kk

    issue(0); CP_COMMIT();

    for (int i = 0; i < 24; i++) {
        if (i + 1 < 24) { issue(i + 1); CP_COMMIT(); CP_WAIT1(); }
        else            { CP_WAIT0(); }
        __syncthreads();

        int buf = i & 1;
        uint32_t ab = aS + buf * (BUFH * 2);
        uint32_t bb = bS + buf * (BUFH * 2);
        #pragma unroll
        for (int kk = 0; kk < 32; kk += 16) {
            uint32_t afr[2][4], bfr[4][4];
            #pragma unroll
            for (int mi = 0; mi < 2; mi++)
                ldsm_x4(afr[mi], ab + (uint32_t)((rA + mi * 16) * PITCH + cA + kk) * 2);
            #pragma unroll
            for (int nj = 0; nj < 4; nj++)
                ldsm_x4(bfr[nj], bb + (uint32_t)((rB + nj * 16) * PITCH + cB + kk) * 2);
            #pragma unroll
            for (int mi = 0; mi < 2; mi++)
                #pragma unroll
                for (int n8 = 0; n8 < 8; n8++)
                    mma_bf16(acc[mi][n8], afr[mi], &bfr[n8 >> 1][(n8 & 1) * 2]);
        }
        __syncthreads();
    }

    // ---------------- epilogue ----------------
    const int quad = lane >> 2, tcol = (lane & 3) * 2;
    #pragma unroll
    for (int mi = 0; mi < 2; mi++) {
        #pragma unroll
        for (int n8 = 0; n8 < 8; n8++) {
            int colt = wn * 64 + n8 * 8 + tcol;          // col within 128 tile
            int col  = cCol * 128 + colt;                // global col
            #pragma unroll
            for (int half = 0; half < 2; half++) {       // c0c1 / c2c3
                int row = cRow * 128 + wm * 32 + mi * 16 + quad + half * 8;
                float v0 = acc[mi][n8][half * 2 + 0];
                float v1 = acc[mi][n8][half * 2 + 1];
                if (EPI == 0) {
                    float f0 = v0 + bias[col], f1 = v1 + bias[col + 1];
                    int b = row / Ln, l = row % Ln;
                    __nv_bfloat162 h = __float22bfloat162_rn(make_float2(f0, f1));
                    *(uint32_t*)((__nv_bfloat16*)Cout +
                        (((size_t)(b * NHn + cCol) * Ln + l) * DHn + colt)) =
                        *reinterpret_cast<uint32_t*>(&h);
                } else if (EPI == 1) {
                    size_t idx = (size_t)row * Cn + col;
                    float2 xv = *(const float2*)(xin + idx);
                    float2 r;
                    r.x = xv.x + gamma[col]     * (v0 + bias[col]);
                    r.y = xv.y + gamma[col + 1] * (v1 + bias[col + 1]);
                    *(float2*)((float*)Cout + idx) = r;
                } else {
                    if (colt < OAW) {
                        float* dst = (float*)Cout + (size_t)row * OAW;
                        dst[colt] = v0 + bias[colt];
                        if (colt + 1 < OAW) dst[colt + 1] = v1 + bias[colt + 1];
                    }
                }
            }
        }
    }
}

// ---------------------------------------------------------------------------
// Bilinear sampling + softmax. One warp per (b,l,h); lane owns 4 channels.
// ---------------------------------------------------------------------------
__global__ void __launch_bounds__(256) sample_kernel(
    const float* __restrict__ refp, const float* __restrict__ offaw,
    const __nv_bfloat16* __restrict__ value, __nv_bfloat16* __restrict__ attn)
{
    int gw   = (blockIdx.x * 256 + threadIdx.x) >> 5;
    int lane = threadIdx.x & 31;
    if (gw >= BLn * NHn) return;
    int h  = gw % NHn;
    int bl = gw / NHn;
    int b  = bl / Ln;

    const float* oa = offaw + (size_t)bl * OAW;
    float lg0 = oa[48 + h * 4 + 0];
    float lg1 = oa[48 + h * 4 + 1];
    float lg2 = oa[48 + h * 4 + 2];
    float lg3 = oa[48 + h * 4 + 3];
    float mx = fmaxf(fmaxf(lg0, lg1), fmaxf(lg2, lg3));
    float e0 = expf(lg0 - mx), e1 = expf(lg1 - mx);
    float e2 = expf(lg2 - mx), e3 = expf(lg3 - mx);
    float inv = 1.0f / (e0 + e1 + e2 + e3);
    float aws[4] = {e0 * inv, e1 * inv, e2 * inv, e3 * inv};

    float rx = refp[bl * 2 + 0];
    float ry = refp[bl * 2 + 1];
    const __nv_bfloat16* vb = value + ((size_t)(b * NHn + h)) * Ln * DHn;

    float4 acc = make_float4(0.f, 0.f, 0.f, 0.f);
    #pragma unroll
    for (int p = 0; p < NPn; p++) {
        float ox = oa[h * 8 + p * 2 + 0];
        float oy = oa[h * 8 + p * 2 + 1];
        float lx = (rx + ox / (float)WSn) * (float)WSn - 0.5f;
        float ly = (ry + oy / (float)HSn) * (float)HSn - 0.5f;
        float x0f = floorf(lx), y0f = floorf(ly);
        float tx = lx - x0f, ty = ly - y0f;
        int x0 = (int)x0f, y0 = (int)y0f;
        float wp = aws[p];
        float cw[4] = {(1.f - tx) * (1.f - ty) * wp,
                       tx * (1.f - ty) * wp,
                       (1.f - tx) * ty * wp,
                       tx * ty * wp};
        int cx[4] = {x0, x0 + 1, x0,     x0 + 1};
        int cy[4] = {y0, y0,     y0 + 1, y0 + 1};
        #pragma unroll
        for (int c = 0; c < 4; c++) {
            int xi = cx[c], yi = cy[c];
            if (xi >= 0 && xi < WSn && yi >= 0 && yi < HSn) {
                const __nv_bfloat162* vp = reinterpret_cast<const __nv_bfloat162*>(
                    vb + (size_t)(yi * WSn + xi) * DHn + lane * 4);
                float2 f01 = __bfloat1622float2(vp[0]);
                float2 f23 = __bfloat1622float2(vp[1]);
                float w = cw[c];
                acc.x += w * f01.x; acc.y += w * f01.y;
                acc.z += w * f23.x; acc.w += w * f23.y;
            }
        }
    }
    __nv_bfloat162 o0 = __float22bfloat162_rn(make_float2(acc.x, acc.y));
    __nv_bfloat162 o1 = __float22bfloat162_rn(make_float2(acc.z, acc.w));
    uint2 pk;
    pk.x = *reinterpret_cast<uint32_t*>(&o0);
    pk.y = *reinterpret_cast<uint32_t*>(&o1);
    *(uint2*)(attn + (size_t)bl * Cn + h * DHn + lane * 4) = pk;
}

// ---------------------------------------------------------------------------
// Launch
// ---------------------------------------------------------------------------
extern "C" void kernel_launch(void* const* d_in, const int* in_sizes, int n_in,
                              void* d_out, int out_size)
{
    const float* x     = (const float*)d_in[0];
    const float* refp  = (const float*)d_in[1];
    const float* feat  = (const float*)d_in[2];
    const float* qn_w  = (const float*)d_in[5];
    const float* qn_b  = (const float*)d_in[6];
    const float* fn_w  = (const float*)d_in[7];
    const float* fn_b  = (const float*)d_in[8];
    const float* gamma = (const float*)d_in[9];
    const float* Wv    = (const float*)d_in[10];
    const float* bv    = (const float*)d_in[11];
    const float* Woff  = (const float*)d_in[12];
    const float* boff  = (const float*)d_in[13];
    const float* Waw   = (const float*)d_in[14];
    const float* baw   = (const float*)d_in[15];
    const float* Wout  = (const float*)d_in[16];
    const float* bout  = (const float*)d_in[17];
    float* out = (float*)d_out;

    __nv_bfloat16 *qb, *fb, *val, *attn, *wvt, *woutt, *wct;
    float *oaw, *bc;
    cudaGetSymbolAddress((void**)&qb,    g_qb);
    cudaGetSymbolAddress((void**)&fb,    g_fb);
    cudaGetSymbolAddress((void**)&val,   g_val);
    cudaGetSymbolAddress((void**)&attn,  g_attn);
    cudaGetSymbolAddress((void**)&oaw,   g_offaw);
    cudaGetSymbolAddress((void**)&wvt,   g_wvt);
    cudaGetSymbolAddress((void**)&woutt, g_woutt);
    cudaGetSymbolAddress((void**)&wct,   g_wct);
    cudaGetSymbolAddress((void**)&bc,    g_bc);

    // Weight prep
    dim3 tb(32, 32);
    wt_kernel<<<dim3(24, 24), tb>>>(Wv,   wvt);
    wt_kernel<<<dim3(24, 24), tb>>>(Wout, woutt);
    comb_kernel<<<(128 * Cn) / 256, 256>>>(Woff, boff, Waw, baw, wct, bc);

    // LayerNorms -> bf16
    ln_kernel<<<BLn, 256>>>(x,    qn_w, qn_b, qb);
    ln_kernel<<<BLn, 256>>>(feat, fn_w, fn_b, fb);

    // value = LN(feat) @ Wv + bv   (bf16, per-head layout)
    gemm_hmma<0><<<dim3(Cn / 128, BLn / 128), 256>>>(
        fb, wvt, bv, val, nullptr, nullptr);

    // offsets + attn logits = LN(x) @ [Woff|Waw] + bias  (fp32, 72 cols)
    gemm_hmma<2><<<dim3(1, BLn / 128), 256>>>(
        qb, wct, bc, oaw, nullptr, nullptr);

    // softmax + bilinear sampling -> attn (bf16)
    sample_kernel<<<(BLn * NHn) / 8, 256>>>(refp, oaw, val, attn);

    // out = x + gamma * (attn @ Wout + bout)
    gemm_hmma<1><<<dim3(Cn / 128, BLn / 128), 256>>>(
        attn, woutt, bout, out, x, gamma);
}

// round 5
// speedup vs baseline: 4.2188x; 1.0694x over previous
#include <cuda_runtime.h>
#include <cuda_bf16.h>
#include <math.h>
#include <stdint.h>

// Problem constants
#define Bn   4
#define Ln   6400
#define Cn   768
#define NHn  6
#define NPn  4
#define DHn  128
#define HSn  80
#define WSn  80
#define BLn  (Bn * Ln)          // 25600 rows
#define OAW  72                 // 48 offset cols + 24 attn-weight cols

// ---------------------------------------------------------------------------
// Scratch (static device globals)
// ---------------------------------------------------------------------------
__device__ __nv_bfloat16 g_qb[BLn * Cn];      // layernorm(x), bf16
__device__ __nv_bfloat16 g_fb[BLn * Cn];      // layernorm(feat), bf16
__device__ __nv_bfloat16 g_val[BLn * Cn];     // value [B][NH][L][DH], bf16
__device__ __nv_bfloat16 g_attn[BLn * Cn];    // sampled attn [B*L][C], bf16
__device__ float         g_offaw[BLn * OAW];  // offsets+logits, fp32
__device__ __nv_bfloat16 g_wvt[Cn * Cn];      // Wv^T  [N][K] bf16
__device__ __nv_bfloat16 g_woutt[Cn * Cn];    // Wout^T [N][K] bf16
__device__ __nv_bfloat16 g_wct[128 * Cn];     // [Woff|Waw|0]^T [128][K] bf16
__device__ float         g_bc[OAW];           // combined bias

// ---------------------------------------------------------------------------
// PTX helpers (portable: mma.sync + ldmatrix + cp.async, all sm_80+)
// ---------------------------------------------------------------------------
__device__ __forceinline__ uint32_t s2u(const void* p) {
    uint32_t a;
    asm("{ .reg .u64 t; cvta.to.shared.u64 t, %1; cvt.u32.u64 %0, t; }"
        : "=r"(a) : "l"(p));
    return a;
}

__device__ __forceinline__ void ldsm_x4(uint32_t* r, uint32_t addr) {
    asm volatile("ldmatrix.sync.aligned.m8n8.x4.shared.b16 {%0,%1,%2,%3}, [%4];"
        : "=r"(r[0]), "=r"(r[1]), "=r"(r[2]), "=r"(r[3]) : "r"(addr));
}
__device__ __forceinline__ void mma_bf16(float* c, const uint32_t* a, const uint32_t* b) {
    asm volatile(
        "mma.sync.aligned.m16n8k16.row.col.f32.bf16.bf16.f32 "
        "{%0,%1,%2,%3}, {%4,%5,%6,%7}, {%8,%9}, {%0,%1,%2,%3};"
        : "+f"(c[0]), "+f"(c[1]), "+f"(c[2]), "+f"(c[3])
        : "r"(a[0]), "r"(a[1]), "r"(a[2]), "r"(a[3]), "r"(b[0]), "r"(b[1]));
}
__device__ __forceinline__ void cp16(uint32_t smem, const void* g) {
    asm volatile("cp.async.cg.shared.global [%0], [%1], 16;" :: "r"(smem), "l"(g));
}
#define CP_COMMIT()  asm volatile("cp.async.commit_group;" ::: "memory")
#define CP_WAIT0()   asm volatile("cp.async.wait_group 0;" ::: "memory")

// ---------------------------------------------------------------------------
// LayerNorm: one WARP per row of 768. 6x float4 per lane, shuffle-only
// reduction, packed bf16x2 stores. No block barriers.
// ---------------------------------------------------------------------------
__global__ void __launch_bounds__(256) ln_kernel(
    const float* __restrict__ in, const float* __restrict__ w,
    const float* __restrict__ b, __nv_bfloat16* __restrict__ out)
{
    const int wid  = threadIdx.x >> 5, lane = threadIdx.x & 31;
    const int row  = blockIdx.x * 8 + wid;
    const float4* p = (const float4*)(in + (size_t)row * Cn);

    float4 v[6];
    #pragma unroll
    for (int i = 0; i < 6; i++) v[i] = p[i * 32 + lane];

    float s1 = 0.f, s2 = 0.f;
    #pragma unroll
    for (int i = 0; i < 6; i++) {
        s1 += v[i].x + v[i].y + v[i].z + v[i].w;
        s2 += v[i].x * v[i].x + v[i].y * v[i].y
            + v[i].z * v[i].z + v[i].w * v[i].w;
    }
    #pragma unroll
    for (int o = 16; o > 0; o >>= 1) {
        s1 += __shfl_xor_sync(0xffffffffu, s1, o);
        s2 += __shfl_xor_sync(0xffffffffu, s2, o);
    }
    float mu = s1 * (1.0f / Cn);
    float rs = rsqrtf(s2 * (1.0f / Cn) - mu * mu + 1e-6f);

    const float4* wv = (const float4*)w;
    const float4* bv = (const float4*)b;
    uint2* o = (uint2*)(out + (size_t)row * Cn);
    #pragma unroll
    for (int i = 0; i < 6; i++) {
        float4 ww = wv[i * 32 + lane];
        float4 bb = bv[i * 32 + lane];
        float f0 = (v[i].x - mu) * rs * ww.x + bb.x;
        float f1 = (v[i].y - mu) * rs * ww.y + bb.y;
        float f2 = (v[i].z - mu) * rs * ww.z + bb.z;
        float f3 = (v[i].w - mu) * rs * ww.w + bb.w;
        __nv_bfloat162 h0 = __float22bfloat162_rn(make_float2(f0, f1));
        __nv_bfloat162 h1 = __float22bfloat162_rn(make_float2(f2, f3));
        uint2 pk;
        pk.x = *reinterpret_cast<uint32_t*>(&h0);
        pk.y = *reinterpret_cast<uint32_t*>(&h1);
        o[i * 32 + lane] = pk;
    }
}

// ---------------------------------------------------------------------------
// Weight prep: transpose 768x768 fp32 -> [N][K] bf16
// ---------------------------------------------------------------------------
__global__ void __launch_bounds__(1024) wt_kernel(
    const float* __restrict__ W, __nv_bfloat16* __restrict__ Wt)
{
    __shared__ float t[32][33];
    int tx = threadIdx.x, ty = threadIdx.y;
    int bx = blockIdx.x, by = blockIdx.y;
    t[ty][tx] = W[(size_t)(by * 32 + ty) * Cn + bx * 32 + tx];
    __syncthreads();
    Wt[(size_t)(bx * 32 + ty) * Cn + by * 32 + tx] = __float2bfloat16(t[tx][ty]);
}

// Combine Woff (768x48) and Waw (768x24) into [128][768] bf16 (zero-padded)
__global__ void __launch_bounds__(256) comb_kernel(
    const float* __restrict__ Woff, const float* __restrict__ boff,
    const float* __restrict__ Waw,  const float* __restrict__ baw,
    __nv_bfloat16* __restrict__ Wct, float* __restrict__ bc)
{
    int idx = blockIdx.x * 256 + threadIdx.x;   // 0 .. 128*768-1
    int j = idx / Cn, k = idx % Cn;
    float v = 0.f;
    if (j < 48)       v = Woff[(size_t)k * 48 + j];
    else if (j < OAW) v = Waw[(size_t)k * 24 + (j - 48)];
    Wct[idx] = __float2bfloat16(v);
    if (idx < OAW) bc[idx] = (idx < 48) ? boff[idx] : baw[idx - 48];
}

// ---------------------------------------------------------------------------
// HMMA bf16 GEMM: C[M,128*gx] = A[M,768] @ Bt^T. CTA tile 128x128, BK=32,
// 8 warps (4 along M x 2 along N), warp tile 32x64, cp.async double buffer,
// single __syncthreads per mainloop iteration (overlapped prefetch).
// SMEM row pitch = 40 halves (80 B) -> conflict-free ldmatrix.
// B stored [N][K] -> NON-trans ldmatrix gives canonical col-major B frag.
// EPI 0: value = acc + bias  -> bf16, layout [B][NH=cCol][L][DH]
// EPI 1: out   = x + gamma * (acc + bias) -> fp32 [M][768]
// EPI 2: offaw = acc + bias (cols < 72)   -> fp32 [M][72]
// ---------------------------------------------------------------------------
#define PITCH 40          // halves per SMEM row (80 B)
#define BUFH  (128 * PITCH)

template <int EPI>
__global__ void __launch_bounds__(256) gemm_hmma(
    const __nv_bfloat16* __restrict__ A,
    const __nv_bfloat16* __restrict__ Bt,
    const float* __restrict__ bias,
    void* __restrict__ Cout,
    const float* __restrict__ xin,
    const float* __restrict__ gamma)
{
    __shared__ __align__(16) __nv_bfloat16 As[2][BUFH];
    __shared__ __align__(16) __nv_bfloat16 Bs[2][BUFH];

    const int tid  = threadIdx.x;
    const int wid  = tid >> 5, lane = tid & 31;
    const int wm   = wid & 3;          // 0..3  (32 rows each)
    const int wn   = wid >> 2;         // 0..1  (64 cols each)
    const int cCol = blockIdx.x, cRow = blockIdx.y;

    const __nv_bfloat16* Ab = A  + (size_t)cRow * 128 * Cn;
    const __nv_bfloat16* Bb = Bt + (size_t)cCol * 128 * Cn;
    const uint32_t aS = s2u(As), bS = s2u(Bs);

    // per-thread gmem/smem chunk coords (2 chunks of 16B per matrix per stage)
    const int row_c[2] = { tid >> 2, (tid + 256) >> 2 };
    const int q_c[2]   = { tid & 3,  tid & 3 };

    auto issue = [&](int i) {
        int buf = i & 1, k0 = i * 32;
        uint32_t ab = aS + buf * (BUFH * 2);
        uint32_t bb = bS + buf * (BUFH * 2);
        #pragma unroll
        for (int it = 0; it < 2; it++) {
            int row = row_c[it], q = q_c[it];
            uint32_t so = (uint32_t)(row * PITCH + q * 8) * 2;
            cp16(ab + so, Ab + (size_t)row * Cn + k0 + q * 8);
            cp16(bb + so, Bb + (size_t)row * Cn + k0 + q * 8);
        }
    };

    float acc[2][8][4];
    #pragma unroll
    for (int mi = 0; mi < 2; mi++)
        #pragma unroll
        for (int n8 = 0; n8 < 8; n8++)
            #pragma unroll
            for (int j = 0; j < 4; j++) acc[mi][n8][j] = 0.f;

    // ldmatrix lane address components
    const int lrow = lane & 7, grp = lane >> 3;
    const int rA = wm * 32 + (grp & 1) * 8 + lrow;         // + mi*16
    const int cA = (grp >> 1) * 8;                         // + kk
    const int rB = wn * 64 + ((lane >> 4) & 1) * 8 + lrow; // + nj*16
    const int cB = (grp & 1) * 8;                          // + kk

    issue(0); CP_COMMIT();

    for (int i = 0; i < 24; i++) {
        CP_WAIT0();              // group i complete (only pending group)
        __syncthreads();         // copies visible; buf (i+1)&1 free to write
        if (i + 1 < 24) { issue(i + 1); CP_COMMIT(); }

        int buf = i & 1;
        uint32_t ab = aS + buf * (BUFH * 2);
        uint32_t bb = bS + buf * (BUFH * 2);
        #pragma unroll
        for (int kk = 0; kk < 32; kk += 16) {
            uint32_t afr[2][4], bfr[4][4];
            #pragma unroll
            for (int mi = 0; mi < 2; mi++)
                ldsm_x4(afr[mi], ab + (uint32_t)((rA + mi * 16) * PITCH + cA + kk) * 2);
            #pragma unroll
            for (int nj = 0; nj < 4; nj++)
                ldsm_x4(bfr[nj], bb + (uint32_t)((rB + nj * 16) * PITCH + cB + kk) * 2);
            #pragma unroll
            for (int mi = 0; mi < 2; mi++)
                #pragma unroll
                for (int n8 = 0; n8 < 8; n8++)
                    mma_bf16(acc[mi][n8], afr[mi], &bfr[n8 >> 1][(n8 & 1) * 2]);
        }
    }

    // ---------------- epilogue ----------------
    const int quad = lane >> 2, tcol = (lane & 3) * 2;
    #pragma unroll
    for (int mi = 0; mi < 2; mi++) {
        #pragma unroll
        for (int n8 = 0; n8 < 8; n8++) {
            int colt = wn * 64 + n8 * 8 + tcol;          // col within 128 tile
            int col  = cCol * 128 + colt;                // global col
            #pragma unroll
            for (int half = 0; half < 2; half++) {       // c0c1 / c2c3
                int row = cRow * 128 + wm * 32 + mi * 16 + quad + half * 8;
                float v0 = acc[mi][n8][half * 2 + 0];
                float v1 = acc[mi][n8][half * 2 + 1];
                if (EPI == 0) {
                    float f0 = v0 + bias[col], f1 = v1 + bias[col + 1];
                    int b = row / Ln, l = row % Ln;
                    __nv_bfloat162 h = __float22bfloat162_rn(make_float2(f0, f1));
                    *(uint32_t*)((__nv_bfloat16*)Cout +
                        (((size_t)(b * NHn + cCol) * Ln + l) * DHn + colt)) =
                        *reinterpret_cast<uint32_t*>(&h);
                } else if (EPI == 1) {
                    size_t idx = (size_t)row * Cn + col;
                    float2 xv = *(const float2*)(xin + idx);
                    float2 r;
                    r.x = xv.x + gamma[col]     * (v0 + bias[col]);
                    r.y = xv.y + gamma[col + 1] * (v1 + bias[col + 1]);
                    *(float2*)((float*)Cout + idx) = r;
                } else {
                    if (colt < OAW) {
                        float* dst = (float*)Cout + (size_t)row * OAW;
                        dst[colt] = v0 + bias[colt];
                        if (colt + 1 < OAW) dst[colt + 1] = v1 + bias[colt + 1];
                    }
                }
            }
        }
    }
}

// ---------------------------------------------------------------------------
// Bilinear sampling + softmax. One warp per (b,l,h); lane owns 4 channels.
// ---------------------------------------------------------------------------
__global__ void __launch_bounds__(256) sample_kernel(
    const float* __restrict__ refp, const float* __restrict__ offaw,
    const __nv_bfloat16* __restrict__ value, __nv_bfloat16* __restrict__ attn)
{
    int gw   = (blockIdx.x * 256 + threadIdx.x) >> 5;
    int lane = threadIdx.x & 31;
    if (gw >= BLn * NHn) return;
    int h  = gw % NHn;
    int bl = gw / NHn;
    int b  = bl / Ln;

    const float* oa = offaw + (size_t)bl * OAW;
    float lg0 = oa[48 + h * 4 + 0];
    float lg1 = oa[48 + h * 4 + 1];
    float lg2 = oa[48 + h * 4 + 2];
    float lg3 = oa[48 + h * 4 + 3];
    float mx = fmaxf(fmaxf(lg0, lg1), fmaxf(lg2, lg3));
    float e0 = expf(lg0 - mx), e1 = expf(lg1 - mx);
    float e2 = expf(lg2 - mx), e3 = expf(lg3 - mx);
    float inv = 1.0f / (e0 + e1 + e2 + e3);
    float aws[4] = {e0 * inv, e1 * inv, e2 * inv, e3 * inv};

    float rx = refp[bl * 2 + 0];
    float ry = refp[bl * 2 + 1];
    const __nv_bfloat16* vb = value + ((size_t)(b * NHn + h)) * Ln * DHn;

    float4 acc = make_float4(0.f, 0.f, 0.f, 0.f);
    #pragma unroll
    for (int p = 0; p < NPn; p++) {
        float ox = oa[h * 8 + p * 2 + 0];
        float oy = oa[h * 8 + p * 2 + 1];
        float lx = (rx + ox / (float)WSn) * (float)WSn - 0.5f;
        float ly = (ry + oy / (float)HSn) * (float)HSn - 0.5f;
        float x0f = floorf(lx), y0f = floorf(ly);
        float tx = lx - x0f, ty = ly - y0f;
        int x0 = (int)x0f, y0 = (int)y0f;
        float wp = aws[p];
        float cw[4] = {(1.f - tx) * (1.f - ty) * wp,
                       tx * (1.f - ty) * wp,
                       (1.f - tx) * ty * wp,
                       tx * ty * wp};
        int cx[4] = {x0, x0 + 1, x0,     x0 + 1};
        int cy[4] = {y0, y0,     y0 + 1, y0 + 1};
        #pragma unroll
        for (int c = 0; c < 4; c++) {
            int xi = cx[c], yi = cy[c];
            if (xi >= 0 && xi < WSn && yi >= 0 && yi < HSn) {
                const __nv_bfloat162* vp = reinterpret_cast<const __nv_bfloat162*>(
                    vb + (size_t)(yi * WSn + xi) * DHn + lane * 4);
                float2 f01 = __bfloat1622float2(vp[0]);
                float2 f23 = __bfloat1622float2(vp[1]);
                float w = cw[c];
                acc.x += w * f01.x; acc.y += w * f01.y;
                acc.z += w * f23.x; acc.w += w * f23.y;
            }
        }
    }
    __nv_bfloat162 o0 = __float22bfloat162_rn(make_float2(acc.x, acc.y));
    __nv_bfloat162 o1 = __float22bfloat162_rn(make_float2(acc.z, acc.w));
    uint2 pk;
    pk.x = *reinterpret_cast<uint32_t*>(&o0);
    pk.y = *reinterpret_cast<uint32_t*>(&o1);
    *(uint2*)(attn + (size_t)bl * Cn + h * DHn + lane * 4) = pk;
}

// ---------------------------------------------------------------------------
// Launch
// ---------------------------------------------------------------------------
extern "C" void kernel_launch(void* const* d_in, const int* in_sizes, int n_in,
                              void* d_out, int out_size)
{
    const float* x     = (const float*)d_in[0];
    const float* refp  = (const float*)d_in[1];
    const float* feat  = (const float*)d_in[2];
    const float* qn_w  = (const float*)d_in[5];
    const float* qn_b  = (const float*)d_in[6];
    const float* fn_w  = (const float*)d_in[7];
    const float* fn_b  = (const float*)d_in[8];
    const float* gamma = (const float*)d_in[9];
    const float* Wv    = (const float*)d_in[10];
    const float* bv    = (const float*)d_in[11];
    const float* Woff  = (const float*)d_in[12];
    const float* boff  = (const float*)d_in[13];
    const float* Waw   = (const float*)d_in[14];
    const float* baw   = (const float*)d_in[15];
    const float* Wout  = (const float*)d_in[16];
    const float* bout  = (const float*)d_in[17];
    float* out = (float*)d_out;

    __nv_bfloat16 *qb, *fb, *val, *attn, *wvt, *woutt, *wct;
    float *oaw, *bc;
    cudaGetSymbolAddress((void**)&qb,    g_qb);
    cudaGetSymbolAddress((void**)&fb,    g_fb);
    cudaGetSymbolAddress((void**)&val,   g_val);
    cudaGetSymbolAddress((void**)&attn,  g_attn);
    cudaGetSymbolAddress((void**)&oaw,   g_offaw);
    cudaGetSymbolAddress((void**)&wvt,   g_wvt);
    cudaGetSymbolAddress((void**)&woutt, g_woutt);
    cudaGetSymbolAddress((void**)&wct,   g_wct);
    cudaGetSymbolAddress((void**)&bc,    g_bc);

    // Weight prep
    dim3 tb(32, 32);
    wt_kernel<<<dim3(24, 24), tb>>>(Wv,   wvt);
    wt_kernel<<<dim3(24, 24), tb>>>(Wout, woutt);
    comb_kernel<<<(128 * Cn) / 256, 256>>>(Woff, boff, Waw, baw, wct, bc);

    // LayerNorms -> bf16 (warp per row)
    ln_kernel<<<BLn / 8, 256>>>(x,    qn_w, qn_b, qb);
    ln_kernel<<<BLn / 8, 256>>>(feat, fn_w, fn_b, fb);

    // value = LN(feat) @ Wv + bv   (bf16, per-head layout)
    gemm_hmma<0><<<dim3(Cn / 128, BLn / 128), 256>>>(
        fb, wvt, bv, val, nullptr, nullptr);

    // offsets + attn logits = LN(x) @ [Woff|Waw] + bias  (fp32, 72 cols)
    gemm_hmma<2><<<dim3(1, BLn / 128), 256>>>(
        qb, wct, bc, oaw, nullptr, nullptr);

    // softmax + bilinear sampling -> attn (bf16)
    sample_kernel<<<(BLn * NHn) / 8, 256>>>(refp, oaw, val, attn);

    // out = x + gamma * (attn @ Wout + bout)
    gemm_hmma<1><<<dim3(Cn / 128, BLn / 128), 256>>>(
        attn, woutt, bout, out, x, gamma);
}